// round 5
// baseline (speedup 1.0000x reference)
#include <cuda_runtime.h>

// AlphaCompositor: N=8, K=8, H=512, W=512, C=4, P=100000
// out = [images (N,C,H,W) f32] ++ [!bg_mask (N,H,W) as f32]
//
// Strategy: the kernel is bound by L1tex wavefront throughput (one wavefront
// per random 16B point gather). Divert ~14% of gathers to the (idle) LDS pipe
// by staging the first SPTS points of the packed table in 224KB of shared
// memory, with a persistent grid so the staging cost is paid once per SM.

#define NN 8
#define KK 8
#define HH 512
#define WW 512
#define CC 4
#define PP 100000
#define HW (HH * WW)

#define SPTS 14336                    // points staged in smem (14336*16B = 224KB)
#define SMEM_BYTES (SPTS * 16)
#define NBLOCKS 148                   // persistent: one CTA per SM (B200 = 148 SMs)
#define NTHREADS 1024

// AoS-packed point features, one float4 per point (1.6 MB, L2-resident).
__device__ float4 g_packed[PP];

__global__ void pack_kernel(const float* __restrict__ ptclds) {
    int p = blockIdx.x * blockDim.x + threadIdx.x;
    if (p < PP) {
        float4 v;
        v.x = __ldg(ptclds + 0 * PP + p);
        v.y = __ldg(ptclds + 1 * PP + p);
        v.z = __ldg(ptclds + 2 * PP + p);
        v.w = __ldg(ptclds + 3 * PP + p);
        g_packed[p] = v;
    }
}

__global__ __launch_bounds__(NTHREADS) void composite_kernel(
    const int*   __restrict__ pix,
    const float* __restrict__ alphas,
    float*       __restrict__ out,
    int write_mask)
{
    extern __shared__ float4 s_tab[];

    // Stage the hot slice of the point table into smem (once per block).
    for (int p = threadIdx.x; p < SPTS; p += NTHREADS)
        s_tab[p] = g_packed[p];
    __syncthreads();

    const int total  = NN * HW;
    const int stride = NBLOCKS * NTHREADS;

    for (int t = blockIdx.x * NTHREADS + threadIdx.x; t < total; t += stride) {
        const int n  = t >> 18;           // / HW  (HW = 262144 = 2^18)
        const int hw = t & (HW - 1);
        const long nbase = (long)n * KK * HW + hw;

        // ---- Phase 1: streaming loads (coalesced) ----
        int   idx[KK];
        float al[KK];
#pragma unroll
        for (int k = 0; k < KK; k++) {
            idx[k] = __ldg(pix    + nbase + (long)k * HW);
            al[k]  = __ldg(alphas + nbase + (long)k * HW);
        }

        // ---- Phase 2: blend weights (FMA chain, no memory) ----
        float w[KK];
        {
            float trans = 1.0f;
#pragma unroll
            for (int k = 0; k < KK; k++) {
                float a = (idx[k] >= 0) ? al[k] : 0.0f;
                w[k] = a * trans;
                trans *= (1.0f - a);
            }
        }

        // ---- Phase 3: hybrid gather (LDS for staged points, LDG otherwise) ----
        float ax = 0.f, ay = 0.f, az = 0.f, aw = 0.f;
#pragma unroll
        for (int k = 0; k < KK; k++) {
            const int i = (idx[k] >= 0) ? idx[k] : 0;   // invalid -> point 0, w=0
            float4 f;
            if (i < SPTS) f = s_tab[i];
            else          f = __ldg(&g_packed[i]);
            ax = fmaf(w[k], f.x, ax);
            ay = fmaf(w[k], f.y, ay);
            az = fmaf(w[k], f.z, az);
            aw = fmaf(w[k], f.w, aw);
        }

        // Background pixel: first index negative -> images = BG = (0,0,0,1)
        const bool bg = (idx[0] < 0);
        if (bg) { ax = 0.f; ay = 0.f; az = 0.f; aw = 1.f; }

        // ---- Stores: [N,C,H,W] images, then mask ----
        const long obase = (long)n * CC * HW + hw;
        out[obase + 0L * HW] = ax;
        out[obase + 1L * HW] = ay;
        out[obase + 2L * HW] = az;
        out[obase + 3L * HW] = aw;

        if (write_mask)
            out[(long)NN * CC * HW + t] = bg ? 0.f : 1.f;
    }
}

extern "C" void kernel_launch(void* const* d_in, const int* in_sizes, int n_in,
                              void* d_out, int out_size) {
    const int*   pix    = (const int*)d_in[0];    // pix_idxs int32 [N,K,H,W]
    const float* alphas = (const float*)d_in[1];  // alphas  f32   [N,K,H,W]
    const float* ptclds = (const float*)d_in[2];  // ptclds  f32   [C,P]
    float* out = (float*)d_out;

    const int images_elems = NN * CC * HW;
    const int write_mask   = (out_size > images_elems) ? 1 : 0;

    // Opt in to 224KB dynamic smem (idempotent; host-side config, not a stream op).
    cudaFuncSetAttribute(composite_kernel,
                         cudaFuncAttributeMaxDynamicSharedMemorySize, SMEM_BYTES);

    pack_kernel<<<(PP + 255) / 256, 256>>>(ptclds);
    composite_kernel<<<NBLOCKS, NTHREADS, SMEM_BYTES>>>(pix, alphas, out, write_mask);
}

// round 6
// speedup vs baseline: 1.8772x; 1.8772x over previous
#include <cuda_runtime.h>

// AlphaCompositor: N=8, K=8, H=512, W=512, C=4, P=100000
// out = [images (N,C,H,W) f32] ++ [!bg_mask (N,H,W) as f32]
//
// Bound by L1tex wavefront throughput (one 128B-line wavefront per random 16B
// point gather; 16.8M of them => ~63us floor). Strategy: saturate L1 queues
// via max occupancy (regs<=32 -> 64 warps/SM) and branch-free gather loop.

#define NN 8
#define KK 8
#define HH 512
#define WW 512
#define CC 4
#define PP 100000
#define HW (HH * WW)

// AoS-packed point features, one float4 per point (1.6 MB, L2-resident).
__device__ float4 g_packed[PP];

__global__ void pack_kernel(const float* __restrict__ ptclds) {
    int p = blockIdx.x * blockDim.x + threadIdx.x;
    if (p < PP) {
        float4 v;
        v.x = __ldg(ptclds + 0 * PP + p);
        v.y = __ldg(ptclds + 1 * PP + p);
        v.z = __ldg(ptclds + 2 * PP + p);
        v.w = __ldg(ptclds + 3 * PP + p);
        g_packed[p] = v;
    }
}

// One pixel per thread; forced to 8 blocks/SM (64 warps) for max L1 pressure.
__global__ __launch_bounds__(256, 8) void composite_kernel(
    const int*   __restrict__ pix,
    const float* __restrict__ alphas,
    float*       __restrict__ out,
    int write_mask)
{
    const int t = blockIdx.x * blockDim.x + threadIdx.x;   // pixel id in [0, N*HW)
    const int n  = t >> 18;          // / HW  (HW = 262144 = 2^18)
    const int hw = t & (HW - 1);
    const long nbase = (long)n * KK * HW + hw;

    // ---- Phase 1: streaming loads (coalesced) ----
    int   idx[KK];
    float al[KK];
#pragma unroll
    for (int k = 0; k < KK; k++) {
        idx[k] = __ldg(pix    + nbase + (long)k * HW);
        al[k]  = __ldg(alphas + nbase + (long)k * HW);
    }

    // ---- Phase 2: blend weights (pure FMA chain) ----
    // Invalid entries (idx<0) get weight exactly 0, so their (clamped) gather
    // contributes exactly 0 -> branch-free gather loop below is exact.
    float w[KK];
    {
        float trans = 1.0f;
#pragma unroll
        for (int k = 0; k < KK; k++) {
            float a = (idx[k] >= 0) ? al[k] : 0.0f;
            w[k] = a * trans;
            trans *= (1.0f - a);
        }
    }

    // ---- Phase 3: branch-free gather + accumulate ----
    float ax = 0.f, ay = 0.f, az = 0.f, aw = 0.f;
#pragma unroll
    for (int k = 0; k < KK; k++) {
        const int i = max(idx[k], 0);          // clamp: invalid -> point 0 (w=0)
        float4 f = __ldg(&g_packed[i]);
        ax = fmaf(w[k], f.x, ax);
        ay = fmaf(w[k], f.y, ay);
        az = fmaf(w[k], f.z, az);
        aw = fmaf(w[k], f.w, aw);
    }

    // Background pixel: first index negative -> images = BG = (0,0,0,1)
    const bool bg = (idx[0] < 0);
    if (bg) { ax = 0.f; ay = 0.f; az = 0.f; aw = 1.f; }

    // ---- Stores: [N,C,H,W] images, then mask ----
    const long obase = (long)n * CC * HW + hw;
    out[obase + 0L * HW] = ax;
    out[obase + 1L * HW] = ay;
    out[obase + 2L * HW] = az;
    out[obase + 3L * HW] = aw;

    if (write_mask)
        out[(long)NN * CC * HW + t] = bg ? 0.f : 1.f;
}

extern "C" void kernel_launch(void* const* d_in, const int* in_sizes, int n_in,
                              void* d_out, int out_size) {
    const int*   pix    = (const int*)d_in[0];    // pix_idxs int32 [N,K,H,W]
    const float* alphas = (const float*)d_in[1];  // alphas  f32   [N,K,H,W]
    const float* ptclds = (const float*)d_in[2];  // ptclds  f32   [C,P]
    float* out = (float*)d_out;

    const int images_elems = NN * CC * HW;
    const int write_mask   = (out_size > images_elems) ? 1 : 0;

    pack_kernel<<<(PP + 255) / 256, 256>>>(ptclds);

    const int total_threads = NN * HW;   // 2097152
    composite_kernel<<<total_threads / 256, 256>>>(pix, alphas, out, write_mask);
}

// round 7
// speedup vs baseline: 1.9308x; 1.0286x over previous
#include <cuda_runtime.h>

// AlphaCompositor: N=8, K=8, H=512, W=512, C=4, P=100000
// out = [images (N,C,H,W) f32] ++ [!bg_mask (N,H,W) as f32]
//
// At the L1TEX address-divergence floor (~1 line-visit/cyc/SM; 16.8M random
// 16B gathers). This revision protects the gather table's L1/L2 residency by
// marking all streaming traffic evict-first (.cs), cutting gather latency
// exposure and L2 sector pressure.

#define NN 8
#define KK 8
#define HH 512
#define WW 512
#define CC 4
#define PP 100000
#define HW (HH * WW)

// AoS-packed point features, one float4 per point (1.6 MB, L2-resident).
__device__ float4 g_packed[PP];

__global__ void pack_kernel(const float* __restrict__ ptclds) {
    int p = blockIdx.x * blockDim.x + threadIdx.x;
    if (p < PP) {
        float4 v;
        v.x = __ldg(ptclds + 0 * PP + p);
        v.y = __ldg(ptclds + 1 * PP + p);
        v.z = __ldg(ptclds + 2 * PP + p);
        v.w = __ldg(ptclds + 3 * PP + p);
        g_packed[p] = v;
    }
}

// One pixel per thread; 8 blocks/SM (regs=32, 64 warps) per R6 measurement.
__global__ __launch_bounds__(256, 8) void composite_kernel(
    const int*   __restrict__ pix,
    const float* __restrict__ alphas,
    float*       __restrict__ out,
    int write_mask)
{
    const int t = blockIdx.x * blockDim.x + threadIdx.x;   // pixel id in [0, N*HW)
    const int n  = t >> 18;          // / HW  (HW = 262144 = 2^18)
    const int hw = t & (HW - 1);
    const long nbase = (long)n * KK * HW + hw;

    // ---- Phase 1: streaming loads, evict-first (don't thrash the table) ----
    int   idx[KK];
    float al[KK];
#pragma unroll
    for (int k = 0; k < KK; k++) {
        idx[k] = __ldcs(pix    + nbase + (long)k * HW);
        al[k]  = __ldcs(alphas + nbase + (long)k * HW);
    }

    // ---- Phase 2: blend weights (pure FMA chain) ----
    // Invalid entries (idx<0) get weight exactly 0, so the clamped gather
    // below contributes exactly 0 -> branch-free and exact.
    float w[KK];
    {
        float trans = 1.0f;
#pragma unroll
        for (int k = 0; k < KK; k++) {
            float a = (idx[k] >= 0) ? al[k] : 0.0f;
            w[k] = a * trans;
            trans *= (1.0f - a);
        }
    }

    // ---- Phase 3: branch-free gather + accumulate (normal cache policy) ----
    float ax = 0.f, ay = 0.f, az = 0.f, aw = 0.f;
#pragma unroll
    for (int k = 0; k < KK; k++) {
        const int i = max(idx[k], 0);          // clamp: invalid -> point 0 (w=0)
        float4 f = __ldg(&g_packed[i]);
        ax = fmaf(w[k], f.x, ax);
        ay = fmaf(w[k], f.y, ay);
        az = fmaf(w[k], f.z, az);
        aw = fmaf(w[k], f.w, aw);
    }

    // Background pixel: first index negative -> images = BG = (0,0,0,1)
    const bool bg = (idx[0] < 0);
    if (bg) { ax = 0.f; ay = 0.f; az = 0.f; aw = 1.f; }

    // ---- Stores: evict-first (pure streaming output) ----
    const long obase = (long)n * CC * HW + hw;
    __stcs(out + obase + 0L * HW, ax);
    __stcs(out + obase + 1L * HW, ay);
    __stcs(out + obase + 2L * HW, az);
    __stcs(out + obase + 3L * HW, aw);

    if (write_mask)
        __stcs(out + (long)NN * CC * HW + t, bg ? 0.f : 1.f);
}

extern "C" void kernel_launch(void* const* d_in, const int* in_sizes, int n_in,
                              void* d_out, int out_size) {
    const int*   pix    = (const int*)d_in[0];    // pix_idxs int32 [N,K,H,W]
    const float* alphas = (const float*)d_in[1];  // alphas  f32   [N,K,H,W]
    const float* ptclds = (const float*)d_in[2];  // ptclds  f32   [C,P]
    float* out = (float*)d_out;

    const int images_elems = NN * CC * HW;
    const int write_mask   = (out_size > images_elems) ? 1 : 0;

    pack_kernel<<<(PP + 255) / 256, 256>>>(ptclds);

    const int total_threads = NN * HW;   // 2097152
    composite_kernel<<<total_threads / 256, 256>>>(pix, alphas, out, write_mask);
}